// round 11
// baseline (speedup 1.0000x reference)
#include <cuda_runtime.h>
#include <cuda_bf16.h>
#include <cuda_fp16.h>
#include <mma.h>
#include <cstdint>

using namespace nvcuda;

#define D 128
#define TR 128            /* tile rows: 8 row-groups x 16 rows */
#define NTH 512
#define NWARP 16
#define LDB 136           /* bf16 smem row stride (mult of 8, odd*8 -> conflict-free LDSM) */
#define LDS 20            /* f32 scratch stride */

/* ---- smem layout (bytes) ---- */
#define OFF_PI0 0                 /* Pi split hi  [128][136] bf16  34816B */
#define OFF_PI1 34816
#define OFF_PI2 69632
#define OFF_X0  104448            /* X split hi (V0 overwrites)    34816B */
#define OFF_X1  139264            /* X split mid (V1 overwrites)          */
#define OFF_X2  174080            /* X split lo                            */
#define OFF_SCR 208896            /* 16 warps x [16][20] f32 = 20480B      */
#define OFF_INV 229376            /* [128] f32 */
#define OFF_NQ  229888            /* [128] f32 */
#define OFF_SI  230400            /* [15] interior boundaries */
#define OFF_SC  230464            /* [16] centroids */
#define SMEM_BYTES 230528

__device__ __forceinline__ uint32_t b2u(__nv_bfloat162 v) {
    return *reinterpret_cast<uint32_t*>(&v);
}

/* split a float pair into 3 bf16x2 words (hi, mid, lo) */
__device__ __forceinline__ void split3(float f0, float f1,
                                       uint32_t &o0, uint32_t &o1, uint32_t &o2) {
    __nv_bfloat162 b0 = __floats2bfloat162_rn(f0, f1);
    float e0 = f0 - __low2float(b0), e1 = f1 - __high2float(b0);
    __nv_bfloat162 b1 = __floats2bfloat162_rn(e0, e1);
    float g0 = e0 - __low2float(b1), g1 = e1 - __high2float(b1);
    __nv_bfloat162 b2 = __floats2bfloat162_rn(g0, g1);
    o0 = b2u(b0); o1 = b2u(b1); o2 = b2u(b2);
}

typedef wmma::fragment<wmma::matrix_a, 16, 16, 16, __nv_bfloat16, wmma::row_major> FragA;
typedef wmma::fragment<wmma::matrix_b, 16, 16, 16, __nv_bfloat16, wmma::col_major> FragBC;
typedef wmma::fragment<wmma::matrix_b, 16, 16, 16, __nv_bfloat16, wmma::row_major> FragBR;
typedef wmma::fragment<wmma::accumulator, 16, 16, 16, float> FragC;

extern "C" __global__ void __launch_bounds__(NTH, 1)
tq_kernel(const float* __restrict__ x, const float* __restrict__ Pi,
          const float* __restrict__ cent, const float* __restrict__ bnd,
          float* __restrict__ out, int nrows, int ntiles)
{
    extern __shared__ char smem[];
    __nv_bfloat16* P0s = (__nv_bfloat16*)(smem + OFF_PI0);
    __nv_bfloat16* P1s = (__nv_bfloat16*)(smem + OFF_PI1);
    __nv_bfloat16* P2s = (__nv_bfloat16*)(smem + OFF_PI2);
    __nv_bfloat16* X0s = (__nv_bfloat16*)(smem + OFF_X0);
    __nv_bfloat16* X1s = (__nv_bfloat16*)(smem + OFF_X1);
    __nv_bfloat16* X2s = (__nv_bfloat16*)(smem + OFF_X2);
    float* INV = (float*)(smem + OFF_INV);
    float* NQ  = (float*)(smem + OFF_NQ);
    float* sI  = (float*)(smem + OFF_SI);
    float* sC  = (float*)(smem + OFF_SC);

    const int t = threadIdx.x;
    const int w = t >> 5;
    const int l = t & 31;
    const int g = w >> 1;            /* row group: rows 16g..16g+15 */
    const int h = w & 1;             /* j/k half */

    if (t < 16) sC[t] = cent[t];
    if (t < 15) sI[t] = bnd[t + 1];

    /* ---- one-time: Pi 3-way bf16 split into smem [j][k], stride 136 ---- */
    {
        int j = t >> 2, k0 = (t & 3) * 32;
        for (int kk = 0; kk < 32; kk++) {
            int k = k0 + kk;
            float f = Pi[j * D + k];
            __nv_bfloat16 b0 = __float2bfloat16_rn(f);
            float e1 = f - __bfloat162float(b0);
            __nv_bfloat16 b1 = __float2bfloat16_rn(e1);
            float e2 = e1 - __bfloat162float(b1);
            P0s[j * LDB + k] = b0;
            P1s[j * LDB + k] = b1;
            P2s[j * LDB + k] = __float2bfloat16_rn(e2);
        }
    }
    __syncthreads();

    float* scr = (float*)(smem + OFF_SCR) + w * 320;   /* [16][20] per warp */
    const int qr  = l >> 1;                            /* scratch row 0..15 */
    const int ch  = l & 1;                             /* col half */
    const int rlw = g * 16 + qr;                       /* this lane's tile row (quant/epi) */

    for (int tile = blockIdx.x; tile < ntiles; tile += gridDim.x) {
        const int row0 = tile * TR;

        /* ---------- stage: gmem -> 3-way bf16 splits in smem + row norms ---------- */
        {
            int r = t >> 2;                 /* row 0..127 */
            int kq = (t & 3) * 32;          /* k quarter */
            int gr = row0 + r;
            float s = 0.f;
            uint32_t* x0p = (uint32_t*)(X0s + r * LDB + kq);
            uint32_t* x1p = (uint32_t*)(X1s + r * LDB + kq);
            uint32_t* x2p = (uint32_t*)(X2s + r * LDB + kq);
            if (gr < nrows) {
                const float4* src = (const float4*)(x + (size_t)gr * D + kq);
                #pragma unroll
                for (int i = 0; i < 8; i++) {
                    float4 v = src[i];
                    s += v.x * v.x + v.y * v.y + v.z * v.z + v.w * v.w;
                    uint32_t a0, a1, a2, c0, c1, c2;
                    split3(v.x, v.y, a0, a1, a2);
                    split3(v.z, v.w, c0, c1, c2);
                    x0p[2 * i] = a0;     x1p[2 * i] = a1;     x2p[2 * i] = a2;
                    x0p[2 * i + 1] = c0; x1p[2 * i + 1] = c1; x2p[2 * i + 1] = c2;
                }
            } else {
                #pragma unroll
                for (int i = 0; i < 16; i++) { x0p[i] = 0u; x1p[i] = 0u; x2p[i] = 0u; }
            }
            s += __shfl_xor_sync(0xffffffffu, s, 1);
            s += __shfl_xor_sync(0xffffffffu, s, 2);
            if ((t & 3) == 0) {
                float nm = sqrtf(s);
                INV[r] = 1.0f / (nm + 1e-8f);
                NQ[r]  = __half2float(__float2half_rn(nm));
            }
        }
        __syncthreads();

        /* ---------- GEMM1: 6 split passes; warp owns jb in {4h..4h+3} ---------- */
        FragC acc[4];
        #pragma unroll
        for (int i = 0; i < 4; i++) wmma::fill_fragment(acc[i], 0.f);
        {
            const __nv_bfloat16* xb = X0s + g * 16 * LDB;
            #pragma unroll
            for (int kb = 0; kb < 8; kb++) {
                FragA a0, a1, a2;
                wmma::load_matrix_sync(a0, xb + kb * 16, LDB);
                wmma::load_matrix_sync(a1, xb + (OFF_X1 - OFF_X0) / 2 + kb * 16, LDB);
                wmma::load_matrix_sync(a2, xb + (OFF_X2 - OFF_X0) / 2 + kb * 16, LDB);
                #pragma unroll
                for (int i = 0; i < 4; i++) {
                    int jb = 4 * h + i;
                    const __nv_bfloat16* pb = P0s + jb * 16 * LDB + kb * 16;
                    FragBC b0, b1, b2;
                    wmma::load_matrix_sync(b0, pb, LDB);
                    wmma::load_matrix_sync(b1, pb + (OFF_PI1 - OFF_PI0) / 2, LDB);
                    wmma::load_matrix_sync(b2, pb + (OFF_PI2 - OFF_PI0) / 2, LDB);
                    wmma::mma_sync(acc[i], a0, b0, acc[i]);
                    wmma::mma_sync(acc[i], a0, b1, acc[i]);
                    wmma::mma_sync(acc[i], a1, b0, acc[i]);
                    wmma::mma_sync(acc[i], a1, b1, acc[i]);
                    wmma::mma_sync(acc[i], a0, b2, acc[i]);
                    wmma::mma_sync(acc[i], a2, b0, acc[i]);
                }
            }
        }
        __syncthreads();   /* all GEMM1 reads of X0s/X1s done before V overwrites */

        /* ---------- quantize: acc -> scratch -> centroids -> V splits over X0/X1 ---------- */
        {
            const float ivn = INV[rlw];
            #pragma unroll
            for (int i = 0; i < 4; i++) {
                int jb = 4 * h + i;
                wmma::store_matrix_sync(scr, acc[i], LDS, wmma::mem_row_major);
                __syncwarp();
                const float* sc2 = scr + qr * LDS + ch * 8;
                uint32_t* v0p = (uint32_t*)(X0s + rlw * LDB + jb * 16 + ch * 8);
                uint32_t* v1p = (uint32_t*)(X1s + rlw * LDB + jb * 16 + ch * 8);
                #pragma unroll
                for (int ii = 0; ii < 4; ii++) {
                    float va = sc2[2 * ii] * ivn;
                    float vb = sc2[2 * ii + 1] * ivn;
                    int ida = (va > sI[7]) ? 8 : 0;
                    ida += (va > sI[ida + 3]) ? 4 : 0;
                    ida += (va > sI[ida + 1]) ? 2 : 0;
                    ida += (va > sI[ida + 0]) ? 1 : 0;
                    int idb = (vb > sI[7]) ? 8 : 0;
                    idb += (vb > sI[idb + 3]) ? 4 : 0;
                    idb += (vb > sI[idb + 1]) ? 2 : 0;
                    idb += (vb > sI[idb + 0]) ? 1 : 0;
                    float ca = sC[ida], cb = sC[idb];
                    __nv_bfloat162 b0 = __floats2bfloat162_rn(ca, cb);
                    float e0 = ca - __low2float(b0), e1 = cb - __high2float(b0);
                    __nv_bfloat162 b1 = __floats2bfloat162_rn(e0, e1);
                    v0p[ii] = b2u(b0);
                    v1p[ii] = b2u(b1);
                }
                __syncwarp();
            }
        }
        __syncthreads();   /* partner's j-half of V must be complete */

        /* ---------- GEMM2: 3 split passes; warp owns kb in {4h..4h+3} ---------- */
        FragC acc2[4];
        #pragma unroll
        for (int i = 0; i < 4; i++) wmma::fill_fragment(acc2[i], 0.f);
        {
            const __nv_bfloat16* vb = X0s + g * 16 * LDB;
            #pragma unroll
            for (int jb = 0; jb < 8; jb++) {
                FragA v0, v1;
                wmma::load_matrix_sync(v0, vb + jb * 16, LDB);
                wmma::load_matrix_sync(v1, vb + (OFF_X1 - OFF_X0) / 2 + jb * 16, LDB);
                #pragma unroll
                for (int i = 0; i < 4; i++) {
                    int kb = 4 * h + i;
                    const __nv_bfloat16* pb = P0s + jb * 16 * LDB + kb * 16;
                    FragBR b0, b1;
                    wmma::load_matrix_sync(b0, pb, LDB);
                    wmma::load_matrix_sync(b1, pb + (OFF_PI1 - OFF_PI0) / 2, LDB);
                    wmma::mma_sync(acc2[i], v0, b0, acc2[i]);
                    wmma::mma_sync(acc2[i], v0, b1, acc2[i]);
                    wmma::mma_sync(acc2[i], v1, b0, acc2[i]);
                }
            }
        }

        /* ---------- epilogue: rescale by fp16-roundtrip norm, coalesced stores ---------- */
        {
            const float nqv = NQ[rlw];
            const int gr = row0 + rlw;
            #pragma unroll
            for (int i = 0; i < 4; i++) {
                int kb = 4 * h + i;
                wmma::store_matrix_sync(scr, acc2[i], LDS, wmma::mem_row_major);
                __syncwarp();
                if (gr < nrows) {
                    const float* s0 = scr + qr * LDS + ch * 8;
                    float* op = out + (size_t)gr * D + kb * 16 + ch * 8;
                    float4 o0 = make_float4(s0[0] * nqv, s0[1] * nqv,
                                            s0[2] * nqv, s0[3] * nqv);
                    float4 o1 = make_float4(s0[4] * nqv, s0[5] * nqv,
                                            s0[6] * nqv, s0[7] * nqv);
                    *(float4*)op = o0;
                    *(float4*)(op + 4) = o1;
                }
                __syncwarp();
            }
        }
        __syncthreads();   /* GEMM2 V reads + epilogue done before next staging */
    }
}

extern "C" void kernel_launch(void* const* d_in, const int* in_sizes, int n_in,
                              void* d_out, int out_size) {
    const float* x    = (const float*)d_in[0];
    const float* Pi   = (const float*)d_in[1];
    const float* cent = (const float*)d_in[2];
    const float* bnd  = (const float*)d_in[3];
    float* out = (float*)d_out;

    int nrows  = in_sizes[0] / D;
    int ntiles = (nrows + TR - 1) / TR;

    cudaFuncSetAttribute(tq_kernel, cudaFuncAttributeMaxDynamicSharedMemorySize,
                         SMEM_BYTES);

    int grid = ntiles < 148 ? ntiles : 148;  /* persistent: 1 CTA/SM */
    tq_kernel<<<grid, NTH, SMEM_BYTES>>>(x, Pi, cent, bnd, out, nrows, ntiles);
}

// round 12
// speedup vs baseline: 1.2747x; 1.2747x over previous
#include <cuda_runtime.h>
#include <cuda_bf16.h>
#include <cuda_fp16.h>
#include <cstdint>

#define D 128
#define TR 128            /* tile rows: 8 warps x 16 rows */
#define NTH 256
#define LDB 136           /* bf16 smem row stride: 272B, odd*16 -> conflict-free ldmatrix */
#define SPL 34816         /* bytes between split planes (128*136*2) */

#define OFF_PI0 0         /* Pi splits [128][136] bf16 x3 */
#define OFF_X0  104448    /* X splits  [128][136] bf16 x3 */
#define OFF_INV 208896    /* [128] f32 */
#define OFF_NQ  209408    /* [128] f32 */
#define SMEM_BYTES 209920

__device__ __forceinline__ uint32_t smem_u32(const void* p) {
    uint32_t a;
    asm("{ .reg .u64 t; cvta.to.shared.u64 t, %1; cvt.u32.u64 %0, t; }" : "=r"(a) : "l"(p));
    return a;
}
__device__ __forceinline__ void ldsm_x4(uint32_t* r, uint32_t addr) {
    asm volatile("ldmatrix.sync.aligned.m8n8.x4.shared.b16 {%0,%1,%2,%3}, [%4];"
                 : "=r"(r[0]), "=r"(r[1]), "=r"(r[2]), "=r"(r[3]) : "r"(addr));
}
__device__ __forceinline__ void ldsm_x4t(uint32_t* r, uint32_t addr) {
    asm volatile("ldmatrix.sync.aligned.m8n8.x4.trans.shared.b16 {%0,%1,%2,%3}, [%4];"
                 : "=r"(r[0]), "=r"(r[1]), "=r"(r[2]), "=r"(r[3]) : "r"(addr));
}
__device__ __forceinline__ void mma16816(float* d, const uint32_t* a,
                                         uint32_t b0, uint32_t b1) {
    asm volatile("mma.sync.aligned.m16n8k16.row.col.f32.bf16.bf16.f32 "
                 "{%0,%1,%2,%3}, {%4,%5,%6,%7}, {%8,%9}, {%0,%1,%2,%3};"
                 : "+f"(d[0]), "+f"(d[1]), "+f"(d[2]), "+f"(d[3])
                 : "r"(a[0]), "r"(a[1]), "r"(a[2]), "r"(a[3]), "r"(b0), "r"(b1));
}
__device__ __forceinline__ uint32_t b2u(__nv_bfloat162 v) {
    return *reinterpret_cast<uint32_t*>(&v);
}
/* branchless searchsorted over 15 register boundaries + shfl centroid gather */
__device__ __forceinline__ float quantv(float v, const float* Bv, float creg) {
    int idx = 0;
    #pragma unroll
    for (int i = 0; i < 15; i++) idx += (v > Bv[i]) ? 1 : 0;
    return __shfl_sync(0xffffffffu, creg, idx);
}
/* split pair into hi/lo packed bf16x2 */
__device__ __forceinline__ void split2p(float a, float b, uint32_t &hi, uint32_t &lo) {
    __nv_bfloat162 h = __floats2bfloat162_rn(a, b);
    float e0 = a - __low2float(h), e1 = b - __high2float(h);
    __nv_bfloat162 l2 = __floats2bfloat162_rn(e0, e1);
    hi = b2u(h); lo = b2u(l2);
}
__device__ __forceinline__ void split3(float f0, float f1,
                                       uint32_t &o0, uint32_t &o1, uint32_t &o2) {
    __nv_bfloat162 b0 = __floats2bfloat162_rn(f0, f1);
    float e0 = f0 - __low2float(b0), e1 = f1 - __high2float(b0);
    __nv_bfloat162 b1 = __floats2bfloat162_rn(e0, e1);
    float g0 = e0 - __low2float(b1), g1 = e1 - __high2float(b1);
    __nv_bfloat162 b2 = __floats2bfloat162_rn(g0, g1);
    o0 = b2u(b0); o1 = b2u(b1); o2 = b2u(b2);
}

extern "C" __global__ void __launch_bounds__(NTH, 1)
tq_kernel(const float* __restrict__ x, const float* __restrict__ Pi,
          const float* __restrict__ cent, const float* __restrict__ bnd,
          float* __restrict__ out, int nrows, int ntiles)
{
    extern __shared__ char smem[];
    const uint32_t sb = smem_u32(smem);
    __nv_bfloat16* P0s = (__nv_bfloat16*)(smem + OFF_PI0);
    __nv_bfloat16* X0s = (__nv_bfloat16*)(smem + OFF_X0);
    float* INV = (float*)(smem + OFF_INV);
    float* NQ  = (float*)(smem + OFF_NQ);

    const int t = threadIdx.x;
    const int w = t >> 5;
    const int l = t & 31;

    /* per-thread tables in registers */
    float Bv[15];
    #pragma unroll
    for (int i = 0; i < 15; i++) Bv[i] = bnd[i + 1];
    const float creg = cent[l & 15];

    /* ---- one-time: Pi 3-way bf16 split into smem [j][k], stride 136 ---- */
    {
        int j = t >> 1, k0 = (t & 1) * 64;
        for (int kk = 0; kk < 64; kk++) {
            int k = k0 + kk;
            float f = Pi[j * D + k];
            __nv_bfloat16 b0 = __float2bfloat16_rn(f);
            float e1 = f - __bfloat162float(b0);
            __nv_bfloat16 b1 = __float2bfloat16_rn(e1);
            float e2 = e1 - __bfloat162float(b1);
            P0s[j * LDB + k] = b0;
            P0s[(SPL / 2) + j * LDB + k] = b1;
            P0s[SPL + j * LDB + k] = __float2bfloat16_rn(e2);
        }
    }
    __syncthreads();

    /* ldmatrix lane offsets (bytes within a 16-row region) */
    const uint32_t offA  = ((l & 7) + ((l >> 3) & 1) * 8) * (LDB * 2) + ((l >> 4) & 1) * 16;
    const uint32_t offB1 = ((l & 7) + ((l >> 4) & 1) * 8) * (LDB * 2) + ((l >> 3) & 1) * 16;
    const uint32_t sbX = sb + OFF_X0;
    const uint32_t sbP = sb + OFF_PI0;
    const int rq = l >> 2;          /* fragment row within 16 (0..7) */

    for (int tile = blockIdx.x; tile < ntiles; tile += gridDim.x) {
        const int row0 = tile * TR;

        /* ---------- stage X: gmem -> 3-way bf16 splits + row norms ---------- */
        {
            int r = t >> 1;
            int h2 = t & 1;
            int gr = row0 + r;
            float s = 0.f;
            uint32_t* x0p = (uint32_t*)(X0s + r * LDB + h2 * 64);
            uint32_t* x1p = (uint32_t*)(X0s + (SPL / 2) + r * LDB + h2 * 64);
            uint32_t* x2p = (uint32_t*)(X0s + SPL + r * LDB + h2 * 64);
            if (gr < nrows) {
                const float4* src = (const float4*)(x + (size_t)gr * D + h2 * 64);
                #pragma unroll
                for (int i = 0; i < 16; i++) {
                    float4 v = src[i];
                    s += v.x * v.x + v.y * v.y + v.z * v.z + v.w * v.w;
                    uint32_t a0, a1, a2, c0, c1, c2;
                    split3(v.x, v.y, a0, a1, a2);
                    split3(v.z, v.w, c0, c1, c2);
                    x0p[2 * i] = a0;     x1p[2 * i] = a1;     x2p[2 * i] = a2;
                    x0p[2 * i + 1] = c0; x1p[2 * i + 1] = c1; x2p[2 * i + 1] = c2;
                }
            } else {
                #pragma unroll
                for (int i = 0; i < 32; i++) { x0p[i] = 0u; x1p[i] = 0u; x2p[i] = 0u; }
            }
            s += __shfl_xor_sync(0xffffffffu, s, 1);
            if (h2 == 0) {
                float nm = sqrtf(s);
                INV[r] = 1.0f / (nm + 1e-8f);
                NQ[r]  = __half2float(__float2half_rn(nm));
            }
        }
        __syncthreads();

        /* ---------- GEMM1: D1[16 rows x 128 j], 6 split passes, all in regs ---------- */
        float d1[16][4];
        #pragma unroll
        for (int j = 0; j < 16; j++) {
            d1[j][0] = 0.f; d1[j][1] = 0.f; d1[j][2] = 0.f; d1[j][3] = 0.f;
        }
        {
            const uint32_t aBase = sbX + (uint32_t)(w * 16) * (LDB * 2) + offA;
            #pragma unroll 2
            for (int kb = 0; kb < 8; kb++) {
                uint32_t a0[4], a1[4], a2[4];
                uint32_t ax = aBase + kb * 32;
                ldsm_x4(a0, ax);
                ldsm_x4(a1, ax + SPL);
                ldsm_x4(a2, ax + 2 * SPL);
                uint32_t bBase = sbP + kb * 32 + offB1;
                #pragma unroll
                for (int jp = 0; jp < 8; jp++) {
                    uint32_t b0[4], b1[4], b2[4];
                    uint32_t bx = bBase + (uint32_t)jp * (16 * LDB * 2);
                    ldsm_x4(b0, bx);
                    ldsm_x4(b1, bx + SPL);
                    ldsm_x4(b2, bx + 2 * SPL);
                    float* e0 = d1[2 * jp];
                    float* e1 = d1[2 * jp + 1];
                    mma16816(e0, a0, b0[0], b0[1]); mma16816(e1, a0, b0[2], b0[3]);
                    mma16816(e0, a0, b1[0], b1[1]); mma16816(e1, a0, b1[2], b1[3]);
                    mma16816(e0, a1, b0[0], b0[1]); mma16816(e1, a1, b0[2], b0[3]);
                    mma16816(e0, a1, b1[0], b1[1]); mma16816(e1, a1, b1[2], b1[3]);
                    mma16816(e0, a0, b2[0], b2[1]); mma16816(e1, a0, b2[2], b2[3]);
                    mma16816(e0, a2, b0[0], b0[1]); mma16816(e1, a2, b0[2], b0[3]);
                }
            }
        }

        /* ---------- quantize IN REGISTERS: acc layout == GEMM2 A-frag layout ---------- */
        const float ivn0 = INV[w * 16 + rq];
        const float ivn1 = INV[w * 16 + rq + 8];
        uint32_t A0r[8][4], A1r[8][4];
        #pragma unroll
        for (int q = 0; q < 8; q++) {
            #pragma unroll
            for (int hh = 0; hh < 2; hh++) {
                int jb = 2 * q + hh;
                float cA = quantv(d1[jb][0] * ivn0, Bv, creg);
                float cB = quantv(d1[jb][1] * ivn0, Bv, creg);
                float cC = quantv(d1[jb][2] * ivn1, Bv, creg);
                float cD = quantv(d1[jb][3] * ivn1, Bv, creg);
                split2p(cA, cB, A0r[q][2 * hh + 0], A1r[q][2 * hh + 0]);
                split2p(cC, cD, A0r[q][2 * hh + 1], A1r[q][2 * hh + 1]);
            }
        }

        /* ---------- GEMM2 (3 split passes) fused with epilogue ---------- */
        const float nq0 = NQ[w * 16 + rq];
        const float nq1 = NQ[w * 16 + rq + 8];
        const int gr0 = row0 + w * 16 + rq;
        float* p0 = out + (size_t)gr0 * D + 2 * (l & 3);
        float* p1 = p0 + (size_t)8 * D;
        const bool ok0 = gr0 < nrows;
        const bool ok1 = (gr0 + 8) < nrows;
        #pragma unroll 2
        for (int kp = 0; kp < 8; kp++) {
            float e0[4] = {0.f, 0.f, 0.f, 0.f};
            float e1[4] = {0.f, 0.f, 0.f, 0.f};
            uint32_t bB = sbP + kp * 32 + offA;   /* trans pattern == offA pattern */
            #pragma unroll
            for (int jb = 0; jb < 8; jb++) {
                uint32_t b0[4], b1[4];
                uint32_t bx = bB + (uint32_t)jb * (16 * LDB * 2);
                ldsm_x4t(b0, bx);
                ldsm_x4t(b1, bx + SPL);
                mma16816(e0, A0r[jb], b0[0], b0[1]); mma16816(e1, A0r[jb], b0[2], b0[3]);
                mma16816(e0, A0r[jb], b1[0], b1[1]); mma16816(e1, A0r[jb], b1[2], b1[3]);
                mma16816(e0, A1r[jb], b0[0], b0[1]); mma16816(e1, A1r[jb], b0[2], b0[3]);
            }
            if (ok0) {
                float2 u0 = make_float2(e0[0] * nq0, e0[1] * nq0);
                float2 u1 = make_float2(e1[0] * nq0, e1[1] * nq0);
                *(float2*)(p0 + (2 * kp) * 8) = u0;
                *(float2*)(p0 + (2 * kp + 1) * 8) = u1;
            }
            if (ok1) {
                float2 v0 = make_float2(e0[2] * nq1, e0[3] * nq1);
                float2 v1 = make_float2(e1[2] * nq1, e1[3] * nq1);
                *(float2*)(p1 + (2 * kp) * 8) = v0;
                *(float2*)(p1 + (2 * kp + 1) * 8) = v1;
            }
        }
        __syncthreads();   /* X smem + INV/NQ reused by next tile's staging */
    }
}

extern "C" void kernel_launch(void* const* d_in, const int* in_sizes, int n_in,
                              void* d_out, int out_size) {
    const float* x    = (const float*)d_in[0];
    const float* Pi   = (const float*)d_in[1];
    const float* cent = (const float*)d_in[2];
    const float* bnd  = (const float*)d_in[3];
    float* out = (float*)d_out;

    int nrows  = in_sizes[0] / D;
    int ntiles = (nrows + TR - 1) / TR;

    cudaFuncSetAttribute(tq_kernel, cudaFuncAttributeMaxDynamicSharedMemorySize,
                         SMEM_BYTES);

    int grid = ntiles < 148 ? ntiles : 148;  /* persistent: 1 CTA/SM */
    tq_kernel<<<grid, NTH, SMEM_BYTES>>>(x, Pi, cent, bnd, out, nrows, ntiles);
}

// round 13
// speedup vs baseline: 1.3461x; 1.0560x over previous
#include <cuda_runtime.h>
#include <cuda_bf16.h>
#include <cuda_fp16.h>
#include <cstdint>

#define D 128
#define NTH 256
#define LDB 136           /* bf16 smem row stride: 272B, odd*16 -> conflict-free ldmatrix */
#define SPL 34816         /* bytes between split planes (128*136*2) */

#define OFF_PI0 0         /* Pi splits [128][136] bf16 x3 */
#define OFF_X0  104448    /* X splits  [128][136] bf16 x3 (warp-exclusive 16-row bands) */
#define OFF_INV 208896    /* [128] f32 */
#define OFF_NQ  209408    /* [128] f32 */
#define SMEM_BYTES 209920

__device__ __forceinline__ uint32_t smem_u32(const void* p) {
    uint32_t a;
    asm("{ .reg .u64 t; cvta.to.shared.u64 t, %1; cvt.u32.u64 %0, t; }" : "=r"(a) : "l"(p));
    return a;
}
__device__ __forceinline__ void ldsm_x4(uint32_t* r, uint32_t addr) {
    asm volatile("ldmatrix.sync.aligned.m8n8.x4.shared.b16 {%0,%1,%2,%3}, [%4];"
                 : "=r"(r[0]), "=r"(r[1]), "=r"(r[2]), "=r"(r[3]) : "r"(addr));
}
__device__ __forceinline__ void ldsm_x4t(uint32_t* r, uint32_t addr) {
    asm volatile("ldmatrix.sync.aligned.m8n8.x4.trans.shared.b16 {%0,%1,%2,%3}, [%4];"
                 : "=r"(r[0]), "=r"(r[1]), "=r"(r[2]), "=r"(r[3]) : "r"(addr));
}
__device__ __forceinline__ void mma16816(float* d, const uint32_t* a,
                                         uint32_t b0, uint32_t b1) {
    asm volatile("mma.sync.aligned.m16n8k16.row.col.f32.bf16.bf16.f32 "
                 "{%0,%1,%2,%3}, {%4,%5,%6,%7}, {%8,%9}, {%0,%1,%2,%3};"
                 : "+f"(d[0]), "+f"(d[1]), "+f"(d[2]), "+f"(d[3])
                 : "r"(a[0]), "r"(a[1]), "r"(a[2]), "r"(a[3]), "r"(b0), "r"(b1));
}
__device__ __forceinline__ uint32_t b2u(__nv_bfloat162 v) {
    return *reinterpret_cast<uint32_t*>(&v);
}
/* branchless searchsorted over 15 register boundaries + shfl centroid gather */
__device__ __forceinline__ float quantv(float v, const float* Bv, float creg) {
    int idx = 0;
    #pragma unroll
    for (int i = 0; i < 15; i++) idx += (v > Bv[i]) ? 1 : 0;
    return __shfl_sync(0xffffffffu, creg, idx);
}
/* split pair into hi/lo packed bf16x2 */
__device__ __forceinline__ void split2p(float a, float b, uint32_t &hi, uint32_t &lo) {
    __nv_bfloat162 h = __floats2bfloat162_rn(a, b);
    float e0 = a - __low2float(h), e1 = b - __high2float(h);
    __nv_bfloat162 l2 = __floats2bfloat162_rn(e0, e1);
    hi = b2u(h); lo = b2u(l2);
}
__device__ __forceinline__ void split3(float f0, float f1,
                                       uint32_t &o0, uint32_t &o1, uint32_t &o2) {
    __nv_bfloat162 b0 = __floats2bfloat162_rn(f0, f1);
    float e0 = f0 - __low2float(b0), e1 = f1 - __high2float(b0);
    __nv_bfloat162 b1 = __floats2bfloat162_rn(e0, e1);
    float g0 = e0 - __low2float(b1), g1 = e1 - __high2float(b1);
    __nv_bfloat162 b2 = __floats2bfloat162_rn(g0, g1);
    o0 = b2u(b0); o1 = b2u(b1); o2 = b2u(b2);
}

extern "C" __global__ void __launch_bounds__(NTH, 1)
tq_kernel(const float* __restrict__ x, const float* __restrict__ Pi,
          const float* __restrict__ cent, const float* __restrict__ bnd,
          float* __restrict__ out, int nrows, int ngroups)
{
    extern __shared__ char smem[];
    const uint32_t sb = smem_u32(smem);
    __nv_bfloat16* P0s = (__nv_bfloat16*)(smem + OFF_PI0);
    __nv_bfloat16* X0s = (__nv_bfloat16*)(smem + OFF_X0);
    float* INV = (float*)(smem + OFF_INV);
    float* NQ  = (float*)(smem + OFF_NQ);

    const int t = threadIdx.x;
    const int w = t >> 5;
    const int l = t & 31;

    /* per-thread tables in registers */
    float Bv[15];
    #pragma unroll
    for (int i = 0; i < 15; i++) Bv[i] = bnd[i + 1];
    const float creg = cent[l & 15];

    /* ---- one-time: Pi 3-way bf16 split into smem [j][k], stride 136 ---- */
    {
        int j = t >> 1, k0 = (t & 1) * 64;
        for (int kk = 0; kk < 64; kk++) {
            int k = k0 + kk;
            float f = Pi[j * D + k];
            __nv_bfloat16 b0 = __float2bfloat16_rn(f);
            float e1 = f - __bfloat162float(b0);
            __nv_bfloat16 b1 = __float2bfloat16_rn(e1);
            float e2 = e1 - __bfloat162float(b1);
            P0s[j * LDB + k] = b0;
            P0s[(SPL / 2) + j * LDB + k] = b1;
            P0s[SPL + j * LDB + k] = __float2bfloat16_rn(e2);
        }
    }
    __syncthreads();   /* only block barrier: Pi visible to all warps */

    /* ldmatrix lane offsets (bytes within a 16-row region) */
    const uint32_t offA  = ((l & 7) + ((l >> 3) & 1) * 8) * (LDB * 2) + ((l >> 4) & 1) * 16;
    const uint32_t offB1 = ((l & 7) + ((l >> 4) & 1) * 8) * (LDB * 2) + ((l >> 3) & 1) * 16;
    const uint32_t sbX = sb + OFF_X0;
    const uint32_t sbP = sb + OFF_PI0;
    const int rq   = l >> 2;         /* fragment row within 16 (0..7) */
    const int rloc = l >> 1;         /* staging row within 16 (0..15) */
    const int h2   = l & 1;          /* staging k-half */

    /* every warp fully independent: own 16-row groups, zero block barriers */
    for (int g0 = blockIdx.x * 8 + w; g0 < ngroups; g0 += gridDim.x * 8) {
        const int row0 = g0 * 16;

        /* ---------- stage (warp-local): gmem -> 3-way bf16 splits + row norms ---------- */
        {
            int r = w * 16 + rloc;
            int gr = row0 + rloc;
            float s = 0.f;
            uint32_t* x0p = (uint32_t*)(X0s + r * LDB + h2 * 64);
            uint32_t* x1p = (uint32_t*)(X0s + (SPL / 2) + r * LDB + h2 * 64);
            uint32_t* x2p = (uint32_t*)(X0s + SPL + r * LDB + h2 * 64);
            if (gr < nrows) {
                const float4* src = (const float4*)(x + (size_t)gr * D + h2 * 64);
                #pragma unroll
                for (int i = 0; i < 16; i++) {
                    float4 v = src[i];
                    s += v.x * v.x + v.y * v.y + v.z * v.z + v.w * v.w;
                    uint32_t a0, a1, a2, c0, c1, c2;
                    split3(v.x, v.y, a0, a1, a2);
                    split3(v.z, v.w, c0, c1, c2);
                    x0p[2 * i] = a0;     x1p[2 * i] = a1;     x2p[2 * i] = a2;
                    x0p[2 * i + 1] = c0; x1p[2 * i + 1] = c1; x2p[2 * i + 1] = c2;
                }
            } else {
                #pragma unroll
                for (int i = 0; i < 32; i++) { x0p[i] = 0u; x1p[i] = 0u; x2p[i] = 0u; }
            }
            s += __shfl_xor_sync(0xffffffffu, s, 1);
            if (h2 == 0) {
                float nm = sqrtf(s);
                INV[r] = 1.0f / (nm + 1e-8f);
                NQ[r]  = __half2float(__float2half_rn(nm));
            }
        }
        __syncwarp();

        /* ---------- GEMM1: D1[16 rows x 128 j], 6 split passes, all in regs ---------- */
        float d1[16][4];
        #pragma unroll
        for (int j = 0; j < 16; j++) {
            d1[j][0] = 0.f; d1[j][1] = 0.f; d1[j][2] = 0.f; d1[j][3] = 0.f;
        }
        {
            const uint32_t aBase = sbX + (uint32_t)(w * 16) * (LDB * 2) + offA;
            #pragma unroll 2
            for (int kb = 0; kb < 8; kb++) {
                uint32_t a0[4], a1[4], a2[4];
                uint32_t ax = aBase + kb * 32;
                ldsm_x4(a0, ax);
                ldsm_x4(a1, ax + SPL);
                ldsm_x4(a2, ax + 2 * SPL);
                uint32_t bBase = sbP + kb * 32 + offB1;
                #pragma unroll
                for (int jp = 0; jp < 8; jp++) {
                    uint32_t b0[4], b1[4], b2[4];
                    uint32_t bx = bBase + (uint32_t)jp * (16 * LDB * 2);
                    ldsm_x4(b0, bx);
                    ldsm_x4(b1, bx + SPL);
                    ldsm_x4(b2, bx + 2 * SPL);
                    float* e0 = d1[2 * jp];
                    float* e1 = d1[2 * jp + 1];
                    mma16816(e0, a0, b0[0], b0[1]); mma16816(e1, a0, b0[2], b0[3]);
                    mma16816(e0, a0, b1[0], b1[1]); mma16816(e1, a0, b1[2], b1[3]);
                    mma16816(e0, a1, b0[0], b0[1]); mma16816(e1, a1, b0[2], b0[3]);
                    mma16816(e0, a1, b1[0], b1[1]); mma16816(e1, a1, b1[2], b1[3]);
                    mma16816(e0, a0, b2[0], b2[1]); mma16816(e1, a0, b2[2], b2[3]);
                    mma16816(e0, a2, b0[0], b0[1]); mma16816(e1, a2, b0[2], b0[3]);
                }
            }
        }

        /* ---------- quantize IN REGISTERS: acc layout == GEMM2 A-frag layout ---------- */
        const float ivn0 = INV[w * 16 + rq];
        const float ivn1 = INV[w * 16 + rq + 8];
        uint32_t A0r[8][4], A1r[8][4];
        #pragma unroll
        for (int q = 0; q < 8; q++) {
            #pragma unroll
            for (int hh = 0; hh < 2; hh++) {
                int jb = 2 * q + hh;
                float cA = quantv(d1[jb][0] * ivn0, Bv, creg);
                float cB = quantv(d1[jb][1] * ivn0, Bv, creg);
                float cC = quantv(d1[jb][2] * ivn1, Bv, creg);
                float cD = quantv(d1[jb][3] * ivn1, Bv, creg);
                split2p(cA, cB, A0r[q][2 * hh + 0], A1r[q][2 * hh + 0]);
                split2p(cC, cD, A0r[q][2 * hh + 1], A1r[q][2 * hh + 1]);
            }
        }

        /* ---------- GEMM2 (3 split passes) fused with epilogue ---------- */
        const float nq0 = NQ[w * 16 + rq];
        const float nq1 = NQ[w * 16 + rq + 8];
        const int gr0 = row0 + rq;
        float* p0 = out + (size_t)gr0 * D + 2 * (l & 3);
        float* p1 = p0 + (size_t)8 * D;
        const bool ok0 = gr0 < nrows;
        const bool ok1 = (gr0 + 8) < nrows;
        #pragma unroll 2
        for (int kp = 0; kp < 8; kp++) {
            float e0[4] = {0.f, 0.f, 0.f, 0.f};
            float e1[4] = {0.f, 0.f, 0.f, 0.f};
            uint32_t bB = sbP + kp * 32 + offA;   /* trans pattern == offA pattern */
            #pragma unroll
            for (int jb = 0; jb < 8; jb++) {
                uint32_t b0[4], b1[4];
                uint32_t bx = bB + (uint32_t)jb * (16 * LDB * 2);
                ldsm_x4t(b0, bx);
                ldsm_x4t(b1, bx + SPL);
                mma16816(e0, A0r[jb], b0[0], b0[1]); mma16816(e1, A0r[jb], b0[2], b0[3]);
                mma16816(e0, A0r[jb], b1[0], b1[1]); mma16816(e1, A0r[jb], b1[2], b1[3]);
                mma16816(e0, A1r[jb], b0[0], b0[1]); mma16816(e1, A1r[jb], b0[2], b0[3]);
            }
            if (ok0) {
                float2 u0 = make_float2(e0[0] * nq0, e0[1] * nq0);
                float2 u1 = make_float2(e1[0] * nq0, e1[1] * nq0);
                *(float2*)(p0 + (2 * kp) * 8) = u0;
                *(float2*)(p0 + (2 * kp + 1) * 8) = u1;
            }
            if (ok1) {
                float2 v0 = make_float2(e0[2] * nq1, e0[3] * nq1);
                float2 v1 = make_float2(e1[2] * nq1, e1[3] * nq1);
                *(float2*)(p1 + (2 * kp) * 8) = v0;
                *(float2*)(p1 + (2 * kp + 1) * 8) = v1;
            }
        }
        __syncwarp();   /* warp-local: X band + INV/NQ reused next group */
    }
}

extern "C" void kernel_launch(void* const* d_in, const int* in_sizes, int n_in,
                              void* d_out, int out_size) {
    const float* x    = (const float*)d_in[0];
    const float* Pi   = (const float*)d_in[1];
    const float* cent = (const float*)d_in[2];
    const float* bnd  = (const float*)d_in[3];
    float* out = (float*)d_out;

    int nrows   = in_sizes[0] / D;
    int ngroups = (nrows + 15) / 16;

    cudaFuncSetAttribute(tq_kernel, cudaFuncAttributeMaxDynamicSharedMemorySize,
                         SMEM_BYTES);

    int grid = 148;  /* persistent: 1 CTA/SM, warps stream independent 16-row groups */
    tq_kernel<<<grid, NTH, SMEM_BYTES>>>(x, Pi, cent, bnd, out, nrows, ngroups);
}

// round 14
// speedup vs baseline: 1.4352x; 1.0662x over previous
#include <cuda_runtime.h>
#include <cuda_bf16.h>
#include <cuda_fp16.h>
#include <cstdint>

#define D 128
#define NTH 256
#define LDB 136           /* Pi smem row stride (bf16): 272B, conflict-free ldmatrix */
#define SPL 34816         /* bytes between Pi split planes */

#define OFF_PI0 0         /* Pi splits [128][136] bf16 x3 = 104448B */
#define OFF_X   104448    /* 8 warps x 8KB raw fp32 bands [kb][row16][64B, swizzled] */
#define SMEM_BYTES 169984

__device__ __forceinline__ uint32_t smem_u32(const void* p) {
    uint32_t a;
    asm("{ .reg .u64 t; cvta.to.shared.u64 t, %1; cvt.u32.u64 %0, t; }" : "=r"(a) : "l"(p));
    return a;
}
__device__ __forceinline__ void ldsm_x4(uint32_t* r, uint32_t addr) {
    asm volatile("ldmatrix.sync.aligned.m8n8.x4.shared.b16 {%0,%1,%2,%3}, [%4];"
                 : "=r"(r[0]), "=r"(r[1]), "=r"(r[2]), "=r"(r[3]) : "r"(addr));
}
__device__ __forceinline__ void ldsm_x4t(uint32_t* r, uint32_t addr) {
    asm volatile("ldmatrix.sync.aligned.m8n8.x4.trans.shared.b16 {%0,%1,%2,%3}, [%4];"
                 : "=r"(r[0]), "=r"(r[1]), "=r"(r[2]), "=r"(r[3]) : "r"(addr));
}
__device__ __forceinline__ void mma16816(float* d, const uint32_t* a,
                                         uint32_t b0, uint32_t b1) {
    asm volatile("mma.sync.aligned.m16n8k16.row.col.f32.bf16.bf16.f32 "
                 "{%0,%1,%2,%3}, {%4,%5,%6,%7}, {%8,%9}, {%0,%1,%2,%3};"
                 : "+f"(d[0]), "+f"(d[1]), "+f"(d[2]), "+f"(d[3])
                 : "r"(a[0]), "r"(a[1]), "r"(a[2]), "r"(a[3]), "r"(b0), "r"(b1));
}
__device__ __forceinline__ void cpasync16(uint32_t dst, const void* src, uint32_t sz) {
    asm volatile("cp.async.cg.shared.global [%0], [%1], 16, %2;"
                 :: "r"(dst), "l"(src), "r"(sz) : "memory");
}
__device__ __forceinline__ uint32_t b2u(__nv_bfloat162 v) {
    return *reinterpret_cast<uint32_t*>(&v);
}
__device__ __forceinline__ float quantv(float v, const float* Bv, float creg) {
    int idx = 0;
    #pragma unroll
    for (int i = 0; i < 15; i++) idx += (v > Bv[i]) ? 1 : 0;
    return __shfl_sync(0xffffffffu, creg, idx);
}
__device__ __forceinline__ void split2p(float a, float b, uint32_t &hi, uint32_t &lo) {
    __nv_bfloat162 h = __floats2bfloat162_rn(a, b);
    float e0 = a - __low2float(h), e1 = b - __high2float(h);
    __nv_bfloat162 l2 = __floats2bfloat162_rn(e0, e1);
    hi = b2u(h); lo = b2u(l2);
}
__device__ __forceinline__ void split3(float f0, float f1,
                                       uint32_t &o0, uint32_t &o1, uint32_t &o2) {
    __nv_bfloat162 b0 = __floats2bfloat162_rn(f0, f1);
    float e0 = f0 - __low2float(b0), e1 = f1 - __high2float(b0);
    __nv_bfloat162 b1 = __floats2bfloat162_rn(e0, e1);
    float g0 = e0 - __low2float(b1), g1 = e1 - __high2float(b1);
    __nv_bfloat162 b2 = __floats2bfloat162_rn(g0, g1);
    o0 = b2u(b0); o1 = b2u(b1); o2 = b2u(b2);
}

extern "C" __global__ void __launch_bounds__(NTH, 1)
tq_kernel(const float* __restrict__ x, const float* __restrict__ Pi,
          const float* __restrict__ cent, const float* __restrict__ bnd,
          float* __restrict__ out, int nrows, int ngroups)
{
    extern __shared__ char smem[];
    const uint32_t sb = smem_u32(smem);
    __nv_bfloat16* P0s = (__nv_bfloat16*)(smem + OFF_PI0);

    const int t = threadIdx.x;
    const int w = t >> 5;
    const int l = t & 31;

    /* per-thread tables in registers */
    float Bv[15];
    #pragma unroll
    for (int i = 0; i < 15; i++) Bv[i] = bnd[i + 1];
    const float creg = cent[l & 15];

    /* ---- one-time: Pi 3-way bf16 split into smem [j][k], stride 136 ---- */
    {
        int j = t >> 1, k0 = (t & 1) * 64;
        for (int kk = 0; kk < 64; kk++) {
            int k = k0 + kk;
            float f = Pi[j * D + k];
            __nv_bfloat16 b0 = __float2bfloat16_rn(f);
            float e1 = f - __bfloat162float(b0);
            __nv_bfloat16 b1 = __float2bfloat16_rn(e1);
            float e2 = e1 - __bfloat162float(b1);
            P0s[j * LDB + k] = b0;
            P0s[(SPL / 2) + j * LDB + k] = b1;
            P0s[SPL + j * LDB + k] = __float2bfloat16_rn(e2);
        }
    }
    __syncthreads();   /* only block barrier: Pi visible to all warps */

    /* ldmatrix lane offsets for Pi (bytes within a 16-row region) */
    const uint32_t offA  = ((l & 7) + ((l >> 3) & 1) * 8) * (LDB * 2) + ((l >> 4) & 1) * 16;
    const uint32_t offB1 = ((l & 7) + ((l >> 4) & 1) * 8) * (LDB * 2) + ((l >> 3) & 1) * 16;
    const uint32_t sbP = sb + OFF_PI0;

    /* band addressing */
    const uint32_t bandS = sb + OFF_X + (uint32_t)w * 8192;   /* cp.async dst */
    const char*    bandP = smem + OFF_X + w * 8192;           /* LDS reads */
    const int rq = l >> 2;           /* fragment row (0..7) */
    const int c  = l & 3;
    const int d4 = ((rq >> 2) & 1) << 2;                      /* read swizzle */
    const uint32_t gA0 = (uint32_t)(c ^ d4) * 8;
    const uint32_t gA1 = (uint32_t)((c + 4) ^ d4) * 8;

    /* prefetch lane mapping: lane covers row l>>1, col-half l&1 */
    const int pr = l >> 1;
    const int ph = l & 1;
    const uint32_t pswz = ((uint32_t)((pr >> 2) & 1)) << 1;   /* chunk xor */

    const int stride = gridDim.x * 8;
    int g = blockIdx.x * 8 + w;

    /* issue 16 cp.async (one 16-row group's worth for this lane) */
    auto prefetch = [&](int grp) {
        int gr = grp * 16 + pr;
        uint32_t sz = (gr < nrows) ? 16u : 0u;
        const char* src = (const char*)(x + (size_t)gr * D + ph * 64);
        uint32_t dstbase = bandS + (uint32_t)pr * 64;
        #pragma unroll
        for (int kb4 = 0; kb4 < 4; kb4++) {
            int kb = ph * 4 + kb4;
            #pragma unroll
            for (int i = 0; i < 4; i++) {
                uint32_t dst = dstbase + (uint32_t)kb * 1024 + (((uint32_t)i ^ pswz) * 16);
                cpasync16(dst, src + kb4 * 64 + i * 16, sz);
            }
        }
        asm volatile("cp.async.commit_group;" ::: "memory");
    };

    if (g < ngroups) prefetch(g);

    for (; g < ngroups; g += stride) {
        const int row0 = g * 16;
        asm volatile("cp.async.wait_group 0;" ::: "memory");
        __syncwarp();

        /* ---------- GEMM1 with fused fragment build + norm accumulation ---------- */
        float d1[16][4];
        #pragma unroll
        for (int j = 0; j < 16; j++) {
            d1[j][0] = 0.f; d1[j][1] = 0.f; d1[j][2] = 0.f; d1[j][3] = 0.f;
        }
        float nA = 0.f, nB = 0.f;
        #pragma unroll 2
        for (int kb = 0; kb < 8; kb++) {
            const char* bk = bandP + kb * 1024;
            float2 xA0 = *(const float2*)(bk + rq * 64 + gA0);
            float2 xA1 = *(const float2*)(bk + rq * 64 + gA1);
            float2 xB0 = *(const float2*)(bk + (rq + 8) * 64 + gA0);
            float2 xB1 = *(const float2*)(bk + (rq + 8) * 64 + gA1);
            nA += xA0.x * xA0.x + xA0.y * xA0.y + xA1.x * xA1.x + xA1.y * xA1.y;
            nB += xB0.x * xB0.x + xB0.y * xB0.y + xB1.x * xB1.x + xB1.y * xB1.y;
            uint32_t f0[4], f1[4], f2[4];
            split3(xA0.x, xA0.y, f0[0], f1[0], f2[0]);
            split3(xB0.x, xB0.y, f0[1], f1[1], f2[1]);
            split3(xA1.x, xA1.y, f0[2], f1[2], f2[2]);
            split3(xB1.x, xB1.y, f0[3], f1[3], f2[3]);
            uint32_t bBase = sbP + kb * 32 + offB1;
            #pragma unroll
            for (int jp = 0; jp < 8; jp++) {
                uint32_t b0[4], b1[4], b2[4];
                uint32_t bx = bBase + (uint32_t)jp * (16 * LDB * 2);
                ldsm_x4(b0, bx);
                ldsm_x4(b1, bx + SPL);
                ldsm_x4(b2, bx + 2 * SPL);
                float* e0 = d1[2 * jp];
                float* e1 = d1[2 * jp + 1];
                mma16816(e0, f0, b0[0], b0[1]); mma16816(e1, f0, b0[2], b0[3]);
                mma16816(e0, f0, b1[0], b1[1]); mma16816(e1, f0, b1[2], b1[3]);
                mma16816(e0, f1, b0[0], b0[1]); mma16816(e1, f1, b0[2], b0[3]);
                mma16816(e0, f1, b1[0], b1[1]); mma16816(e1, f1, b1[2], b1[3]);
                mma16816(e0, f0, b2[0], b2[1]); mma16816(e1, f0, b2[2], b2[3]);
                mma16816(e0, f2, b0[0], b0[1]); mma16816(e1, f2, b0[2], b0[3]);
            }
        }
        __syncwarp();   /* whole warp done reading band */
        {
            int gn = g + stride;
            if (gn < ngroups) prefetch(gn);   /* overlaps quantize + GEMM2 */
        }

        /* ---------- norms: 2-shfl reduce within the 4-lane c-group ---------- */
        nA += __shfl_xor_sync(0xffffffffu, nA, 1);
        nA += __shfl_xor_sync(0xffffffffu, nA, 2);
        nB += __shfl_xor_sync(0xffffffffu, nB, 1);
        nB += __shfl_xor_sync(0xffffffffu, nB, 2);
        const float nmA = sqrtf(nA), nmB = sqrtf(nB);
        const float ivn0 = 1.0f / (nmA + 1e-8f);
        const float ivn1 = 1.0f / (nmB + 1e-8f);
        const float nq0 = __half2float(__float2half_rn(nmA));
        const float nq1 = __half2float(__float2half_rn(nmB));

        /* ---------- quantize IN REGISTERS: acc layout == GEMM2 A-frag layout ---------- */
        uint32_t A0r[8][4], A1r[8][4];
        #pragma unroll
        for (int q = 0; q < 8; q++) {
            #pragma unroll
            for (int hh = 0; hh < 2; hh++) {
                int jb = 2 * q + hh;
                float cA = quantv(d1[jb][0] * ivn0, Bv, creg);
                float cB = quantv(d1[jb][1] * ivn0, Bv, creg);
                float cC = quantv(d1[jb][2] * ivn1, Bv, creg);
                float cD = quantv(d1[jb][3] * ivn1, Bv, creg);
                split2p(cA, cB, A0r[q][2 * hh + 0], A1r[q][2 * hh + 0]);
                split2p(cC, cD, A0r[q][2 * hh + 1], A1r[q][2 * hh + 1]);
            }
        }

        /* ---------- GEMM2 (3 split passes) fused with epilogue ---------- */
        const int gr0 = row0 + rq;
        float* p0 = out + (size_t)gr0 * D + 2 * c;
        float* p1 = p0 + (size_t)8 * D;
        const bool ok0 = gr0 < nrows;
        const bool ok1 = (gr0 + 8) < nrows;
        #pragma unroll 2
        for (int kp = 0; kp < 8; kp++) {
            float e0[4] = {0.f, 0.f, 0.f, 0.f};
            float e1[4] = {0.f, 0.f, 0.f, 0.f};
            uint32_t bB = sbP + kp * 32 + offA;   /* trans pattern == offA pattern */
            #pragma unroll
            for (int jb = 0; jb < 8; jb++) {
                uint32_t b0[4], b1[4];
                uint32_t bx = bB + (uint32_t)jb * (16 * LDB * 2);
                ldsm_x4t(b0, bx);
                ldsm_x4t(b1, bx + SPL);
                mma16816(e0, A0r[jb], b0[0], b0[1]); mma16816(e1, A0r[jb], b0[2], b0[3]);
                mma16816(e0, A0r[jb], b1[0], b1[1]); mma16816(e1, A0r[jb], b1[2], b1[3]);
                mma16816(e0, A1r[jb], b0[0], b0[1]); mma16816(e1, A1r[jb], b0[2], b0[3]);
            }
            if (ok0) {
                float2 u0 = make_float2(e0[0] * nq0, e0[1] * nq0);
                float2 u1 = make_float2(e1[0] * nq0, e1[1] * nq0);
                *(float2*)(p0 + (2 * kp) * 8) = u0;
                *(float2*)(p0 + (2 * kp + 1) * 8) = u1;
            }
            if (ok1) {
                float2 v0 = make_float2(e0[2] * nq1, e0[3] * nq1);
                float2 v1 = make_float2(e1[2] * nq1, e1[3] * nq1);
                *(float2*)(p1 + (2 * kp) * 8) = v0;
                *(float2*)(p1 + (2 * kp + 1) * 8) = v1;
            }
        }
    }
}

extern "C" void kernel_launch(void* const* d_in, const int* in_sizes, int n_in,
                              void* d_out, int out_size) {
    const float* x    = (const float*)d_in[0];
    const float* Pi   = (const float*)d_in[1];
    const float* cent = (const float*)d_in[2];
    const float* bnd  = (const float*)d_in[3];
    float* out = (float*)d_out;

    int nrows   = in_sizes[0] / D;
    int ngroups = (nrows + 15) / 16;

    cudaFuncSetAttribute(tq_kernel, cudaFuncAttributeMaxDynamicSharedMemorySize,
                         SMEM_BYTES);

    int grid = 148;  /* persistent: 1 CTA/SM, warps stream independent 16-row groups */
    tq_kernel<<<grid, NTH, SMEM_BYTES>>>(x, Pi, cent, bnd, out, nrows, ngroups);
}